// round 1
// baseline (speedup 1.0000x reference)
#include <cuda_runtime.h>

#define NT   365
#define NB   2048
#define NXD  32
#define HID  256
#define NG   1024   // 4*HID

// ---- device-global scratch (no cudaMalloc allowed) ----
__device__ float g_x0[(size_t)NT * NB * HID];   // relu(x @ w_in^T + b_in), 765 MB
__device__ float g_hbuf[2 * NB * HID];          // double-buffered h state
__device__ float g_c[NB * HID];                 // c state
__device__ float g_bias[NG];                    // b_ih + b_hh

// =====================================================================
// init: zero states, fold biases, preset out = b_out
// =====================================================================
__global__ void init_kernel(const float* __restrict__ b_ih,
                            const float* __restrict__ b_hh,
                            const float* __restrict__ b_out,
                            float* __restrict__ out) {
    int i = blockIdx.x * blockDim.x + threadIdx.x;
    int stride = gridDim.x * blockDim.x;
    for (int k = i; k < 2 * NB * HID; k += stride) g_hbuf[k] = 0.f;
    for (int k = i; k < NB * HID; k += stride) g_c[k] = 0.f;
    for (int k = i; k < NG; k += stride) g_bias[k] = b_ih[k] + b_hh[k];
    float b0 = b_out[0];
    for (int k = i; k < NT * NB; k += stride) out[k] = b0;
}

// =====================================================================
// input projection: x0 = relu(x @ w_in^T + b_in)
// block = 256 threads (one per hidden unit), 32 rows per block
// =====================================================================
__global__ void __launch_bounds__(256) input_proj(const float* __restrict__ x,
                                                  const float* __restrict__ w_in,
                                                  const float* __restrict__ b_in) {
    __shared__ float xs[32][NXD];
    int tid = threadIdx.x;
    size_t row0 = (size_t)blockIdx.x * 32;
    const float* xsrc = x + row0 * NXD;
#pragma unroll
    for (int r = 0; r < 4; ++r) {
        int lin = tid + r * 256;
        xs[lin >> 5][lin & 31] = xsrc[lin];
    }
    float w[NXD];
#pragma unroll
    for (int n = 0; n < NXD; ++n) w[n] = w_in[tid * NXD + n];
    float b = b_in[tid];
    __syncthreads();
    float* dst = g_x0 + row0 * HID + tid;
#pragma unroll 4
    for (int m = 0; m < 32; ++m) {
        float acc = b;
#pragma unroll
        for (int n = 0; n < NXD; ++n) acc = fmaf(xs[m][n], w[n], acc);
        dst[(size_t)m * HID] = fmaxf(acc, 0.f);
    }
}

// =====================================================================
// recurrent step:
//   gates[b, G] = sum_k [x0[t]|h_prev][b,k] * [w_ih|w_hh][G,k] + bias[G]
//   cell update + h_next + partial output dot (atomicAdd)
// Tile: 64 batch rows x 32 hidden units (= 128 gate columns).
// Gate column interleave: local col c -> gate g4 = c&3, unit jj = c>>2.
// 128 threads, each an 8(row) x 4(col-pair) micro-tile via fma.rn.f32x2.
// =====================================================================
__global__ void __launch_bounds__(128) lstm_step(const float* __restrict__ w_ih,
                                                 const float* __restrict__ w_hh,
                                                 const float* __restrict__ w_out,
                                                 float* __restrict__ out,
                                                 int t) {
    __shared__ float smem[64 * 132];          // 33.8 KB, reused for gate staging
    float* As = smem;                          // [64][32]
    float* Bs = smem + 64 * 32;                // [32][132] (pad 4 vs banks)

    int tid = threadIdx.x;
    int tx = tid & 15, ty = tid >> 4;          // 16 x 8
    int b0 = blockIdx.x * 64;
    int j0 = blockIdx.y * 32;

    const float* hin  = g_hbuf + (size_t)(t & 1) * NB * HID;
    float*       hout = g_hbuf + (size_t)((t + 1) & 1) * NB * HID;
    const float* x0t  = g_x0 + (size_t)t * NB * HID;

    unsigned long long acc2[8][4];
#pragma unroll
    for (int i = 0; i < 8; ++i)
#pragma unroll
        for (int p = 0; p < 4; ++p) acc2[i][p] = 0ull;

#pragma unroll 1
    for (int kt = 0; kt < 16; ++kt) {
        int phase = kt >> 3;
        int k0 = (kt & 7) * 32;
        const float* Aptr = phase ? hin : x0t;
        const float* W = phase ? w_hh : w_ih;

        // A tile: 64x32 floats, 4 float4 per thread, coalesced
#pragma unroll
        for (int r = 0; r < 4; ++r) {
            int lin = tid + r * 128;
            int m = lin >> 3, k4 = lin & 7;
            float4 v = *(const float4*)(Aptr + (size_t)(b0 + m) * HID + k0 + k4 * 4);
            *(float4*)(As + m * 32 + k4 * 4) = v;
        }
        // B tile: 128 cols x 32 k, transposed store into Bs[kk][c]
#pragma unroll
        for (int r = 0; r < 8; ++r) {
            int lin = tid + r * 128;
            int c = lin >> 3, k4 = lin & 7;
            int gidx = (c & 3) * HID + j0 + (c >> 2);
            float4 v = *(const float4*)(W + (size_t)gidx * HID + k0 + k4 * 4);
            float* bp = Bs + (k4 * 4) * 132 + c;
            bp[0] = v.x; bp[132] = v.y; bp[264] = v.z; bp[396] = v.w;
        }
        __syncthreads();

#pragma unroll 8
        for (int kk = 0; kk < 32; ++kk) {
            unsigned long long rb2[4], ra2[8];
#pragma unroll
            for (int p = 0; p < 4; ++p)
                rb2[p] = *(const unsigned long long*)(Bs + kk * 132 + ((p * 16 + tx) << 1));
#pragma unroll
            for (int i = 0; i < 8; ++i) {
                float a = As[(i * 8 + ty) * 32 + kk];
                asm("mov.b64 %0, {%1, %1};" : "=l"(ra2[i]) : "f"(a));
            }
#pragma unroll
            for (int i = 0; i < 8; ++i)
#pragma unroll
                for (int p = 0; p < 4; ++p)
                    asm("fma.rn.f32x2 %0, %1, %2, %0;"
                        : "+l"(acc2[i][p]) : "l"(ra2[i]), "l"(rb2[p]));
        }
        __syncthreads();
    }

    // stage gates to smem: gs[m][c], row stride 132
    float* gs = smem;
#pragma unroll
    for (int i = 0; i < 8; ++i)
#pragma unroll
        for (int p = 0; p < 4; ++p)
            *(unsigned long long*)(gs + (i * 8 + ty) * 132 + ((p * 16 + tx) << 1)) = acc2[i][p];
    __syncthreads();

    // cell update: thread -> one batch row m = tid>>1, 16 consecutive jj
    {
        int m = tid >> 1;
        int jbase = (tid & 1) * 16;
        int b = b0 + m;
        const float* gsr = gs + m * 132;
        float osum = 0.f;
#pragma unroll
        for (int s = 0; s < 16; ++s) {
            int jj = jbase + s;
            float4 gv = *(const float4*)(gsr + jj * 4);   // i,f,g,o interleaved
            int j = j0 + jj;
            float gi = gv.x + g_bias[j];
            float gf = gv.y + g_bias[HID + j];
            float gg = gv.z + g_bias[2 * HID + j];
            float go = gv.w + g_bias[3 * HID + j];
            float ii = 1.f / (1.f + __expf(-gi));
            float ff = 1.f / (1.f + __expf(-gf));
            float tg = tanhf(gg);
            float oo = 1.f / (1.f + __expf(-go));
            size_t idx = (size_t)b * HID + j;
            float cn = ff * g_c[idx] + ii * tg;
            float hn = oo * tanhf(cn);
            g_c[idx] = cn;
            hout[idx] = hn;
            osum = fmaf(hn, w_out[j], osum);
        }
        atomicAdd(out + (size_t)t * NB + b, osum);
    }
}

// =====================================================================
extern "C" void kernel_launch(void* const* d_in, const int* in_sizes, int n_in,
                              void* d_out, int out_size) {
    const float* x     = (const float*)d_in[0];
    const float* w_in  = (const float*)d_in[1];
    const float* b_in  = (const float*)d_in[2];
    const float* w_ih  = (const float*)d_in[3];
    const float* w_hh  = (const float*)d_in[4];
    const float* b_ih  = (const float*)d_in[5];
    const float* b_hh  = (const float*)d_in[6];
    const float* w_out = (const float*)d_in[7];
    const float* b_out = (const float*)d_in[8];
    float* out = (float*)d_out;

    init_kernel<<<1024, 256>>>(b_ih, b_hh, b_out, out);
    input_proj<<<(NT * NB) / 32, 256>>>(x, w_in, b_in);

    dim3 sgrid(NB / 64, HID / 32);
    for (int t = 0; t < NT; ++t) {
        lstm_step<<<sgrid, 128>>>(w_ih, w_hh, w_out, out, t);
    }
}